// round 2
// baseline (speedup 1.0000x reference)
#include <cuda_runtime.h>

#define Bc   64
#define LATc 256
#define STc  32
#define Nc   256
#define Ec   32
#define Hc   64
#define NEc  (Nc*Ec)

// Scratch (device globals: no allocation allowed)
__device__ float g_h [Bc*Hc];          // hidden layer       [64,64]
__device__ float g_a [Bc*Nc*Hc];       // ne@We1_top + be1   [64,256,64]
__device__ float g_bp[Bc*Nc*Hc];       // ne@We1_bot         [64,256,64]

// ---------------------------------------------------------------------------
// Kernel 1: h = relu(concat(z, stats) @ W1 + b1)     grid=64, block=64
// ---------------------------------------------------------------------------
__global__ void k_hidden(const float* __restrict__ z, const float* __restrict__ st,
                         const float* __restrict__ W1, const float* __restrict__ b1) {
    int b = blockIdx.x, t = threadIdx.x;
    const float* zb = z  + b * LATc;
    const float* sb = st + b * STc;
    float acc = b1[t];
    #pragma unroll 8
    for (int k = 0; k < LATc; ++k) acc += zb[k] * W1[k * Hc + t];
    #pragma unroll
    for (int k = 0; k < STc;  ++k) acc += sb[k] * W1[(LATc + k) * Hc + t];
    g_h[b * Hc + t] = fmaxf(acc, 0.f);
}

// ---------------------------------------------------------------------------
// Kernel 2: node_emb = h @ W2 + b2; then per-node edge-layer projections:
//   a  = ne @ We1[0:32]  + be1
//   bp = ne @ We1[32:64]
// grid = 256 nodes, block = 256 (8 warps, each warp sweeps batches)
// ---------------------------------------------------------------------------
__global__ void k_node(const float* __restrict__ W2,  const float* __restrict__ b2,
                       const float* __restrict__ We1, const float* __restrict__ be1) {
    int i   = blockIdx.x;
    int tid = threadIdx.x;
    int w   = tid >> 5, l = tid & 31;

    __shared__ float W2s[64][32];    // W2 column block for this node (8 KB)
    __shared__ float ne_s[8][33];    // per-warp node embedding

    for (int idx = tid; idx < 64 * 32; idx += 256) {
        int k = idx >> 5, e = idx & 31;
        W2s[k][e] = W2[k * NEc + i * Ec + e];
    }
    __syncthreads();

    for (int b = w; b < Bc; b += 8) {
        const float* hb = g_h + b * Hc;
        float acc = b2[i * Ec + l];
        #pragma unroll
        for (int k = 0; k < 64; ++k) acc += hb[k] * W2s[k][l];
        ne_s[w][l] = acc;
        __syncwarp();

        float a0 = be1[l], a1 = be1[l + 32], p0 = 0.f, p1 = 0.f;
        #pragma unroll
        for (int e = 0; e < 32; ++e) {
            float ne = ne_s[w][e];
            a0 += ne * We1[e        * Hc + l];
            a1 += ne * We1[e        * Hc + l + 32];
            p0 += ne * We1[(Ec + e) * Hc + l];
            p1 += ne * We1[(Ec + e) * Hc + l + 32];
        }
        size_t o = ((size_t)b * Nc + i) * Hc;
        g_a [o + l] = a0;  g_a [o + l + 32] = a1;
        g_bp[o + l] = p0;  g_bp[o + l + 32] = p1;
        __syncwarp();
    }
}

// ---------------------------------------------------------------------------
// Kernel 3: zero the diagonal (output is poisoned to 0xAA)
// ---------------------------------------------------------------------------
__global__ void k_diag(float* __restrict__ out) {
    int b = blockIdx.x, i = threadIdx.x;  // 256 threads
    out[(size_t)b * Nc * Nc + (size_t)i * Nc + i] = 0.f;
}

// ---------------------------------------------------------------------------
// Kernel 4: edge MLP over all upper-triangular pairs.
//   e1 = relu(a_i + bp_j); e2 = relu(e1 @ We2 + be2); logit = e2 @ We3 + be3
// Tiling: 32x32 node tile per block (36 upper tiles x 64 batches).
// Per warp-iteration: 8 pairs sharing one i-row, consecutive j.
// Lane layout: half s = l>>4 handles pairs p0+s*4..+3; cols c0=(l&15)*4.
// We2 row read once per k (LDS.128, dedup'd), applied to 4 register pairs.
// ---------------------------------------------------------------------------
__global__ __launch_bounds__(256)
void k_edges(const float* __restrict__ We2, const float* __restrict__ be2,
             const float* __restrict__ We3, const float* __restrict__ be3,
             float* __restrict__ out) {
    __shared__ float a_s[32][64];   // 8 KB
    __shared__ float b_s[32][65];   // 8.3 KB (pad: 2-word broadcast bank safety)
    __shared__ float W2s[64][64];   // 16 KB

    int tid = threadIdx.x;
    int w = tid >> 5, l = tid & 31;
    int b = blockIdx.y;

    // decode upper-triangular tile (ti <= tj) from linear id
    int L = blockIdx.x, ti = 0;
    while (L >= 8 - ti) { L -= 8 - ti; ++ti; }
    int tj = ti + L;

    const float* ga = g_a  + ((size_t)b * Nc + ti * 32) * Hc;
    const float* gb = g_bp + ((size_t)b * Nc + tj * 32) * Hc;

    for (int idx = tid * 4; idx < 2048; idx += 1024)
        *(float4*)((float*)a_s + idx) = *(const float4*)(ga + idx);
    for (int idx = tid; idx < 2048; idx += 256)
        b_s[idx >> 6][idx & 63] = gb[idx];
    for (int idx = tid * 4; idx < 4096; idx += 1024)
        *(float4*)((float*)W2s + idx) = *(const float4*)(We2 + idx);

    int s  = l >> 4;
    int c0 = (l & 15) * 4;
    float4 be2v = *(const float4*)(be2 + c0);
    float w30 = We3[c0], w31 = We3[c0 + 1], w32 = We3[c0 + 2], w33 = We3[c0 + 3];
    float b3  = be3[0];
    __syncthreads();

    float* outb = out + (size_t)b * Nc * Nc;

    for (int it = 0; it < 16; ++it) {
        int g     = it * 8 + w;      // pair group (8 pairs, same i-row)
        int p0    = g * 8;
        int iL    = p0 >> 5;
        int jbase = (p0 & 31) + s * 4;

        float4 acc[4];
        acc[0] = be2v; acc[1] = be2v; acc[2] = be2v; acc[3] = be2v;

        #pragma unroll 16
        for (int k = 0; k < 64; ++k) {
            float4 wv = *(const float4*)(&W2s[k][c0]);
            float  ak = a_s[iL][k];
            #pragma unroll
            for (int r = 0; r < 4; ++r) {
                float e1 = fmaxf(ak + b_s[jbase + r][k], 0.f);
                acc[r].x += e1 * wv.x;
                acc[r].y += e1 * wv.y;
                acc[r].z += e1 * wv.z;
                acc[r].w += e1 * wv.w;
            }
        }

        int gi = ti * 32 + iL;
        #pragma unroll
        for (int r = 0; r < 4; ++r) {
            float part = fmaxf(acc[r].x, 0.f) * w30 + fmaxf(acc[r].y, 0.f) * w31
                       + fmaxf(acc[r].z, 0.f) * w32 + fmaxf(acc[r].w, 0.f) * w33;
            part += __shfl_xor_sync(0xffffffffu, part, 1);
            part += __shfl_xor_sync(0xffffffffu, part, 2);
            part += __shfl_xor_sync(0xffffffffu, part, 4);
            part += __shfl_xor_sync(0xffffffffu, part, 8);
            int gj = tj * 32 + jbase + r;
            if ((l & 15) == 0 && gj > gi) {
                float logit = part + b3;
                outb[(size_t)gi * Nc + gj] = logit;
                outb[(size_t)gj * Nc + gi] = logit;
            }
        }
    }
}

// ---------------------------------------------------------------------------
extern "C" void kernel_launch(void* const* d_in, const int* in_sizes, int n_in,
                              void* d_out, int out_size) {
    const float* z   = (const float*)d_in[0];
    const float* st  = (const float*)d_in[1];
    const float* W1  = (const float*)d_in[2];
    const float* b1  = (const float*)d_in[3];
    const float* W2  = (const float*)d_in[4];
    const float* b2  = (const float*)d_in[5];
    const float* We1 = (const float*)d_in[6];
    const float* be1 = (const float*)d_in[7];
    const float* We2 = (const float*)d_in[8];
    const float* be2 = (const float*)d_in[9];
    const float* We3 = (const float*)d_in[10];
    const float* be3 = (const float*)d_in[11];
    float* out = (float*)d_out;

    k_hidden<<<Bc, Hc>>>(z, st, W1, b1);
    k_node  <<<Nc, 256>>>(W2, b2, We1, be1);
    k_diag  <<<Bc, 256>>>(out);
    k_edges <<<dim3(36, Bc), 256>>>(We2, be2, We3, be3, out);
}